// round 10
// baseline (speedup 1.0000x reference)
#include <cuda_runtime.h>
#include <math.h>

#define Hh 2048
#define Wd 2048
#define MASKM 2047
#define Kk 16
#define Pp 15
#define TSTRIDE 144   // gather halo tile row stride
#define NTILES 2048   // 16 x-tiles * 128 y-tiles
#define PGRID 1184    // 148 SMs * 8 blocks

// scratch (static device globals — no allocation)
__device__ float g_win[Hh * Wd];
__device__ float g_C;
__device__ int   g_dfast[Kk];   // smem-relative deltas (padded to 16, w=0)
__device__ float g_wfast[Kk];   // weights premultiplied by 1/3375
__device__ int   g_ng;          // out-of-range shifts (never in practice)
__device__ int   g_gsy[Kk], g_gsx[Kk];
__device__ float g_gw[Kk];      // premultiplied by 1/3375

// ---------------------------------------------------------------------------
// Kernel 1: fused separable 15x15 box-sum (zero-padded above/left).
// win[i][j] = sum_{a=i-15..i-1, b=j-15..j-1} img[a][b]
// Tile 128 rows x 64 cols; rowsum staged in SMEM (143 x 64, stride 65).
// Phase 1 uses warp-wide shuffle prefix scans: 2 coalesced loads + ~12 shfl
// per 32 outputs (vs strided LDG.128 -> 8-9 wavefronts each before).
// Block (0,0) additionally does ALL prep work with fully-parallel dedupe.
// grid = (32, 16), 256 threads.
// ---------------------------------------------------------------------------
__global__ void __launch_bounds__(256)
k_box(const float* __restrict__ img,
      const float* __restrict__ patterns,
      const float* __restrict__ vectors) {
    __shared__ float rs[143 * 65];

    int t = threadIdx.x;
    int lane = t & 31;
    int wrp  = t >> 5;
    int j0 = blockIdx.x * 64;
    int i0 = blockIdx.y * 128;

    // ---- prep (block (0,0) only) ----
    if (blockIdx.x == 0 && blockIdx.y == 0) {
        __shared__ float red[256];
        __shared__ int shy[Kk], shx[Kk];
        __shared__ int srare;
        const float scale = 1.0f / 3375.0f;

        if (t == 0) srare = 0;
        if (t < Kk) {
            float vy = __ldg(vectors + 2 * t);
            float vx = __ldg(vectors + 2 * t + 1);
            int ny = ((int)floorf(vy)) & MASKM; if (ny >= 1024) ny -= 2048;
            int nx = ((int)floorf(vx)) & MASKM; if (nx >= 1024) nx -= 2048;
            shy[t] = ny; shx[t] = nx;
        }
        float s = 0.f;
        for (int i = t; i < 900; i += 256) {   // 3600 floats = 900 float4
            float4 f = __ldg((const float4*)patterns + i);
            s += f.x + f.y + f.z + f.w;
        }
        red[t] = s;
        __syncthreads();
        for (int off = 128; off > 0; off >>= 1) {
            if (t < off) red[t] += red[t + off];
            __syncthreads();
        }
        if (t < Kk) {
            int ny = shy[t], nx = shx[t];
            int cnt = 0, first = Kk;
            #pragma unroll
            for (int m = 0; m < Kk; m++) {
                bool eq = (shy[m] == ny) && (shx[m] == nx);
                cnt += eq ? 1 : 0;
                if (eq && m < first) first = m;
            }
            bool isfirst = (first == t);
            bool inr = (ny >= -8 && ny <= 8 && nx >= -8 && nx <= 8);
            if (isfirst && inr) {
                g_dfast[t] = -ny * TSTRIDE - nx;
                g_wfast[t] = (float)cnt * scale;
            } else {
                g_dfast[t] = 0;
                g_wfast[t] = 0.f;
            }
            if (isfirst && !inr) {
                int idx = atomicAdd(&srare, 1);
                g_gsy[idx] = ny; g_gsx[idx] = nx;
                g_gw[idx] = (float)cnt * scale;
            }
        }
        __syncthreads();
        if (t == 0) {
            g_ng = srare;
            g_C = ((float)Kk - red[0] / (float)(Pp * Pp)) / (float)(Kk - 1);
        }
        __syncthreads();
    }

    // ---- phase 1: rowsum via warp shuffle-scan ----
    // task = (row r in 0..142, chunk in {0,1} of 32 cols)
    // rs[r][c] = sum img[i0-15+r][j0+c-15 .. j0+c-1], zero-padded left/top.
    for (int task = wrp; task < 143 * 2; task += 8) {
        int r = task >> 1;
        int chunk = task & 1;
        int arow = i0 - 15 + r;
        int c0 = chunk * 32;
        float S;
        if (arow < 0) {
            S = 0.f;
        } else {
            const float* row = img + (size_t)arow * Wd;
            int gbase = j0 + c0;
            int ga = gbase - 16 + lane;           // u0 cols
            int gb = gbase + 16 + lane;           // u1 cols (lanes 0..15)
            float u0 = (ga >= 0) ? __ldg(row + ga) : 0.f;
            float u1 = (lane < 16) ? __ldg(row + gb) : 0.f;
            // inclusive scan of u0 over 32 lanes
            float p0 = u0;
            #pragma unroll
            for (int d = 1; d < 32; d <<= 1) {
                float o = __shfl_up_sync(0xFFFFFFFFu, p0, d);
                if (lane >= d) p0 += o;
            }
            // inclusive scan of u1 over first 16 lanes + carry
            float p1 = u1;
            #pragma unroll
            for (int d = 1; d < 16; d <<= 1) {
                float o = __shfl_up_sync(0xFFFFFFFFu, p1, d);
                if (lane >= d) p1 += o;
            }
            p1 += __shfl_sync(0xFFFFFFFFu, p0, 31);
            // S[lane] = Q[lane+15] - Q[lane]
            float qa = __shfl_sync(0xFFFFFFFFu, p0, (lane + 15) & 31);
            float qb = __shfl_sync(0xFFFFFFFFu, p1, (lane + 15) & 31);
            S = ((lane <= 16) ? qa : qb) - p0;
        }
        rs[r * 65 + c0 + lane] = S;
    }
    __syncthreads();

    // ---- phase 2: vertical sliding sum -> win (8-row chains) ----
    // 1024 tasks: col 0..63 x 16 row-groups of 8.
    for (int tt = t; tt < 1024; tt += 256) {
        int col = tt & 63;
        int R0  = (tt >> 6) * 8;
        const float* cp = rs + col;
        float s = 0.f;
        #pragma unroll
        for (int r = 0; r < 15; r++) s += cp[(R0 + r) * 65];
        float* outp = g_win + (size_t)(i0 + R0) * Wd + j0 + col;
        #pragma unroll
        for (int rr = 0; rr < 8; rr++) {
            outp[(size_t)rr * Wd] = s;
            if (rr < 7)
                s += cp[(R0 + rr + 15) * 65] - cp[(R0 + rr) * 65];
        }
    }
}

// ---------------------------------------------------------------------------
// Kernel 2: out[i,j] = C + sum_m w'_m * win[(i-sy)&M][(j-sx)&M]
// (weights premultiplied by 1/3375)
// Persistent: 1184 blocks (one full wave @ 8/SM), each strides over the
// 2048 16x128 tiles. 32x144 halo in SMEM (18KB). Branch-free unrolled
// 16-entry fast loop; rare uniform fallback. regs forced to 32 (R8-proven).
// ---------------------------------------------------------------------------
__global__ void __launch_bounds__(256, 8) k_gather(float* __restrict__ out) {
    __shared__ float tile[32 * TSTRIDE];
    __shared__ int   sd[Kk];
    __shared__ float sw[Kk];
    __shared__ int   sng;
    __shared__ float sC;

    int t = threadIdx.x;
    if (t < Kk) { sd[t] = g_dfast[t]; sw[t] = g_wfast[t]; }
    if (t == 0) { sng = g_ng; sC = g_C; }
    __syncthreads();

    int tx = t & 127;
    int R0 = (t >> 7) * 8;   // 0 or 8

    for (int tid = blockIdx.x; tid < NTILES; tid += PGRID) {
        int j0 = (tid & 15) * 128;
        int i0 = (tid >> 4) * 16;

        // stage 32 x 144 halo via float4 (j0-8 ≡ 0 mod 4; wrap never splits)
        for (int idx = t; idx < 32 * 36; idx += 256) {
            int u  = idx / 36;
            int vq = idx - u * 36;
            int gr = (i0 - 8 + u) & MASKM;
            int gc = (j0 - 8 + 4 * vq) & MASKM;
            float4 f = __ldg((const float4*)(g_win + (size_t)gr * Wd + gc));
            *(float4*)&tile[u * TSTRIDE + 4 * vq] = f;
        }
        __syncthreads();

        const float* base = tile + (R0 + 8) * TSTRIDE + tx + 8;

        float acc[8];
        #pragma unroll
        for (int rr = 0; rr < 8; rr++) acc[rr] = 0.f;

        #pragma unroll
        for (int m = 0; m < Kk; m++) {
            float w = sw[m];
            const float* p = base + sd[m];
            #pragma unroll
            for (int rr = 0; rr < 8; rr++)
                acc[rr] += w * p[rr * TSTRIDE];
        }

        int ng = sng;
        if (ng > 0) {  // uniform, essentially never taken
            for (int m = 0; m < ng; m++) {
                int sy = g_gsy[m], sx = g_gsx[m];
                float w = g_gw[m];
                int gc = (j0 + tx - sx) & MASKM;
                #pragma unroll 1
                for (int rr = 0; rr < 8; rr++) {
                    int gr = (i0 + R0 + rr - sy) & MASKM;
                    acc[rr] += w * __ldg(g_win + (size_t)gr * Wd + gc);
                }
            }
        }

        float c = sC;
        float* op = out + (size_t)(i0 + R0) * Wd + j0 + tx;
        #pragma unroll
        for (int rr = 0; rr < 8; rr++)
            op[(size_t)rr * Wd] = c + acc[rr];

        __syncthreads();   // protect tile[] before next stage
    }
}

// ---------------------------------------------------------------------------
extern "C" void kernel_launch(void* const* d_in, const int* in_sizes, int n_in,
                              void* d_out, int out_size) {
    const float* x        = (const float*)d_in[0];  // (1,1,2048,2048)
    const float* patterns = (const float*)d_in[1];  // (16,15,15)
    const float* vectors  = (const float*)d_in[2];  // (16,2)
    float* out = (float*)d_out;                     // (2048,2048)

    k_box<<<dim3(32, 16), 256>>>(x, patterns, vectors);
    k_gather<<<PGRID, 256>>>(out);
}

// round 11
// speedup vs baseline: 1.2979x; 1.2979x over previous
#include <cuda_runtime.h>
#include <math.h>

#define Hh 2048
#define Wd 2048
#define MASKM 2047
#define Kk 16
#define Pp 15
#define TSTRIDE 144   // gather halo tile row stride

// scratch (static device globals — no allocation)
__device__ float g_win[Hh * Wd];
__device__ float g_C;
__device__ int   g_nf;          // number of live fast entries (<= 16)
__device__ int   g_dfast[Kk];   // smem-relative deltas (padded to 16, w=0)
__device__ float g_wfast[Kk];   // weights premultiplied by 1/3375
__device__ int   g_ng;          // out-of-range shifts (never in practice)
__device__ int   g_gsy[Kk], g_gsx[Kk];
__device__ float g_gw[Kk];      // premultiplied by 1/3375

// ---------------------------------------------------------------------------
// Kernel 1: fused separable 15x15 box-sum (zero-padded above/left).
// win[i][j] = sum_{a=i-15..i-1, b=j-15..j-1} img[a][b]
// Tile: 128 rows x 64 cols per block; rowsum staged in SMEM (143 x 64,
// stride 65). grid = (32, 16), 256 threads.
// Block (0,0) additionally does ALL prep work with fully-parallel dedupe.
// (R8-proven version, unchanged.)
// ---------------------------------------------------------------------------
__global__ void __launch_bounds__(256)
k_box(const float* __restrict__ img,
      const float* __restrict__ patterns,
      const float* __restrict__ vectors) {
    __shared__ float rs[143 * 65];

    int t = threadIdx.x;
    int j0 = blockIdx.x * 64;
    int i0 = blockIdx.y * 128;

    // ---- prep (block (0,0) only) ----
    if (blockIdx.x == 0 && blockIdx.y == 0) {
        __shared__ float red[256];
        __shared__ int shy[Kk], shx[Kk];
        __shared__ int srare, sfast;
        const float scale = 1.0f / 3375.0f;

        if (t == 0) { srare = 0; sfast = 0; }
        if (t < Kk) {
            float vy = __ldg(vectors + 2 * t);
            float vx = __ldg(vectors + 2 * t + 1);
            int ny = ((int)floorf(vy)) & MASKM; if (ny >= 1024) ny -= 2048;
            int nx = ((int)floorf(vx)) & MASKM; if (nx >= 1024) nx -= 2048;
            shy[t] = ny; shx[t] = nx;
        }
        float s = 0.f;
        for (int i = t; i < 900; i += 256) {   // 3600 floats = 900 float4
            float4 f = __ldg((const float4*)patterns + i);
            s += f.x + f.y + f.z + f.w;
        }
        red[t] = s;
        __syncthreads();
        for (int off = 128; off > 0; off >>= 1) {
            if (t < off) red[t] += red[t + off];
            __syncthreads();
        }
        // clear fast list (so unused slots are benign zero-weight entries)
        if (t < Kk) { g_dfast[t] = 0; g_wfast[t] = 0.f; }
        __syncthreads();
        if (t < Kk) {
            int ny = shy[t], nx = shx[t];
            int cnt = 0, first = Kk;
            #pragma unroll
            for (int m = 0; m < Kk; m++) {
                bool eq = (shy[m] == ny) && (shx[m] == nx);
                cnt += eq ? 1 : 0;
                if (eq && m < first) first = m;
            }
            bool isfirst = (first == t);
            bool inr = (ny >= -8 && ny <= 8 && nx >= -8 && nx <= 8);
            if (isfirst && inr) {
                int idx = atomicAdd(&sfast, 1);   // pack live entries first
                g_dfast[idx] = -ny * TSTRIDE - nx;
                g_wfast[idx] = (float)cnt * scale;
            }
            if (isfirst && !inr) {
                int idx = atomicAdd(&srare, 1);
                g_gsy[idx] = ny; g_gsx[idx] = nx;
                g_gw[idx] = (float)cnt * scale;
            }
        }
        __syncthreads();
        if (t == 0) {
            g_ng = srare;
            g_nf = sfast;
            g_C = ((float)Kk - red[0] / (float)(Pp * Pp)) / (float)(Kk - 1);
        }
        __syncthreads();
    }

    // ---- phase 1: horizontal sliding sum into rs ----
    for (int tt = t; tt < 143 * 8; tt += 256) {
        int r   = tt >> 3;
        int seg = tt & 7;
        int arow = i0 - 15 + r;
        int jb = j0 + seg * 8;
        float o[8];
        if (arow < 0) {
            #pragma unroll
            for (int c = 0; c < 8; c++) o[c] = 0.f;
        } else {
            const float* row = img + (size_t)arow * Wd;
            float v[24];
            if (jb >= 16) {
                const float4* p = (const float4*)(row + jb - 16);
                #pragma unroll
                for (int q = 0; q < 6; q++) {
                    float4 f = __ldg(p + q);
                    v[4 * q + 0] = f.x; v[4 * q + 1] = f.y;
                    v[4 * q + 2] = f.z; v[4 * q + 3] = f.w;
                }
            } else {
                #pragma unroll
                for (int x = 0; x < 24; x++) {
                    int c = jb - 16 + x;
                    v[x] = (c >= 0) ? __ldg(row + c) : 0.f;
                }
            }
            float s = 0.f;
            #pragma unroll
            for (int x = 1; x <= 15; x++) s += v[x];
            o[0] = s;
            #pragma unroll
            for (int c = 1; c < 8; c++) { s += v[15 + c] - v[c]; o[c] = s; }
        }
        float* dst = rs + r * 65 + seg * 8;
        #pragma unroll
        for (int c = 0; c < 8; c++) dst[c] = o[c];
    }
    __syncthreads();

    // ---- phase 2: vertical sliding sum -> win ----
    int col = t & 63;
    int R0  = (t >> 6) * 32;
    const float* cp = rs + col;
    float s = 0.f;
    #pragma unroll
    for (int r = 0; r < 15; r++) s += cp[(R0 + r) * 65];
    float* outp = g_win + (size_t)(i0 + R0) * Wd + j0 + col;
    #pragma unroll
    for (int rr = 0; rr < 32; rr++) {
        outp[(size_t)rr * Wd] = s;
        if (rr < 31)
            s += cp[(R0 + rr + 15) * 65] - cp[(R0 + rr) * 65];
    }
}

// ---------------------------------------------------------------------------
// Kernel 2: out[i,j] = C + sum_m w'_m * win[(i-sy)&M][(j-sx)&M]
// 16x128 tile/block; 32x144 halo in SMEM (18KB, 8 blocks/SM, regs=32 —
// R8-proven shape). NEW: instead of always running 16 entries, a uniform
// branch picks the smallest fully-unrolled variant covering nf live
// entries (8/10/12/14/16) — typically ~10 for floor(N(0,1)) offsets,
// cutting main-loop LDS traffic ~35%.
// grid = (16, 128), 256 threads; thread = 1 col x 8 rows (x2 groups).
// ---------------------------------------------------------------------------
#define GATHER_LOOP(NM)                                        \
    _Pragma("unroll")                                          \
    for (int m = 0; m < (NM); m++) {                           \
        float w = sw[m];                                       \
        const float* p = base + sd[m];                         \
        _Pragma("unroll")                                      \
        for (int rr = 0; rr < 8; rr++)                         \
            acc[rr] += w * p[rr * TSTRIDE];                    \
    }

__global__ void __launch_bounds__(256, 8) k_gather(float* __restrict__ out) {
    __shared__ float tile[32 * TSTRIDE];
    __shared__ int   sd[Kk];
    __shared__ float sw[Kk];
    __shared__ int   sng, snf;
    __shared__ float sC;

    int t = threadIdx.x;
    int j0 = blockIdx.x * 128;
    int i0 = blockIdx.y * 16;

    if (t < Kk) { sd[t] = g_dfast[t]; sw[t] = g_wfast[t]; }
    if (t == 0) { sng = g_ng; snf = g_nf; sC = g_C; }

    // stage 32 x 144 halo via float4 (j0-8 ≡ 0 mod 4; wrap never splits)
    for (int idx = t; idx < 32 * 36; idx += 256) {
        int u  = idx / 36;
        int vq = idx - u * 36;
        int gr = (i0 - 8 + u) & MASKM;
        int gc = (j0 - 8 + 4 * vq) & MASKM;
        float4 f = __ldg((const float4*)(g_win + (size_t)gr * Wd + gc));
        *(float4*)&tile[u * TSTRIDE + 4 * vq] = f;
    }
    __syncthreads();

    int tx = t & 127;
    int R0 = (t >> 7) * 8;   // 0 or 8
    const float* base = tile + (R0 + 8) * TSTRIDE + tx + 8;

    float acc[8];
    #pragma unroll
    for (int rr = 0; rr < 8; rr++) acc[rr] = 0.f;

    int nf = snf;
    if (nf <= 8)       { GATHER_LOOP(8)  }
    else if (nf <= 10) { GATHER_LOOP(10) }
    else if (nf <= 12) { GATHER_LOOP(12) }
    else if (nf <= 14) { GATHER_LOOP(14) }
    else               { GATHER_LOOP(16) }

    int ng = sng;
    if (ng > 0) {  // uniform, essentially never taken
        for (int m = 0; m < ng; m++) {
            int sy = g_gsy[m], sx = g_gsx[m];
            float w = g_gw[m];
            int gc = (j0 + tx - sx) & MASKM;
            #pragma unroll 1
            for (int rr = 0; rr < 8; rr++) {
                int gr = (i0 + R0 + rr - sy) & MASKM;
                acc[rr] += w * __ldg(g_win + (size_t)gr * Wd + gc);
            }
        }
    }

    float c = sC;
    float* op = out + (size_t)(i0 + R0) * Wd + j0 + tx;
    #pragma unroll
    for (int rr = 0; rr < 8; rr++)
        op[(size_t)rr * Wd] = c + acc[rr];
}

// ---------------------------------------------------------------------------
extern "C" void kernel_launch(void* const* d_in, const int* in_sizes, int n_in,
                              void* d_out, int out_size) {
    const float* x        = (const float*)d_in[0];  // (1,1,2048,2048)
    const float* patterns = (const float*)d_in[1];  // (16,15,15)
    const float* vectors  = (const float*)d_in[2];  // (16,2)
    float* out = (float*)d_out;                     // (2048,2048)

    k_box<<<dim3(32, 16), 256>>>(x, patterns, vectors);
    k_gather<<<dim3(16, 128), 256>>>(out);
}

// round 12
// speedup vs baseline: 1.3101x; 1.0094x over previous
#include <cuda_runtime.h>
#include <math.h>

#define Hh 2048
#define Wd 2048
#define MASKM 2047
#define Kk 16
#define Pp 15
#define TSTRIDE 144   // gather halo tile row stride

// scratch (static device globals — no allocation)
__device__ float g_win[Hh * Wd];
__device__ float g_C;
__device__ int   g_nf;          // number of live fast entries (<= 16)
__device__ int   g_dfast[Kk];   // smem-relative deltas (padded, w=0)
__device__ float g_wfast[Kk];   // weights premultiplied by 1/3375
__device__ int   g_ng;          // out-of-range shifts (never in practice)
__device__ int   g_gsy[Kk], g_gsx[Kk];
__device__ float g_gw[Kk];      // premultiplied by 1/3375

// ---------------------------------------------------------------------------
// Kernel 1: fused separable 15x15 box-sum (zero-padded above/left).
// win[i][j] = sum_{a=i-15..i-1, b=j-15..j-1} img[a][b]
// Tile: 128 rows x 64 cols per block; rowsum staged in SMEM (143 x 64,
// stride 65). grid = (32, 16), 512 threads.
// Phase 1: 16 outputs/thread (8 aligned float4 loads -> 2x amplification).
// Block (0,0) additionally does ALL prep work with fully-parallel dedupe.
// ---------------------------------------------------------------------------
__global__ void __launch_bounds__(512)
k_box(const float* __restrict__ img,
      const float* __restrict__ patterns,
      const float* __restrict__ vectors) {
    __shared__ float rs[143 * 65];

    int t = threadIdx.x;
    int j0 = blockIdx.x * 64;
    int i0 = blockIdx.y * 128;

    // ---- prep (block (0,0) only) ----
    if (blockIdx.x == 0 && blockIdx.y == 0) {
        __shared__ float red[512];
        __shared__ int shy[Kk], shx[Kk];
        __shared__ int srare, sfast;
        const float scale = 1.0f / 3375.0f;

        if (t == 0) { srare = 0; sfast = 0; }
        if (t < Kk) {
            float vy = __ldg(vectors + 2 * t);
            float vx = __ldg(vectors + 2 * t + 1);
            int ny = ((int)floorf(vy)) & MASKM; if (ny >= 1024) ny -= 2048;
            int nx = ((int)floorf(vx)) & MASKM; if (nx >= 1024) nx -= 2048;
            shy[t] = ny; shx[t] = nx;
        }
        float s = 0.f;
        for (int i = t; i < 900; i += 512) {   // 3600 floats = 900 float4
            float4 f = __ldg((const float4*)patterns + i);
            s += f.x + f.y + f.z + f.w;
        }
        red[t] = s;
        __syncthreads();
        for (int off = 256; off > 0; off >>= 1) {
            if (t < off) red[t] += red[t + off];
            __syncthreads();
        }
        if (t < Kk) { g_dfast[t] = 0; g_wfast[t] = 0.f; }
        __syncthreads();
        if (t < Kk) {
            int ny = shy[t], nx = shx[t];
            int cnt = 0, first = Kk;
            #pragma unroll
            for (int m = 0; m < Kk; m++) {
                bool eq = (shy[m] == ny) && (shx[m] == nx);
                cnt += eq ? 1 : 0;
                if (eq && m < first) first = m;
            }
            bool isfirst = (first == t);
            bool inr = (ny >= -8 && ny <= 8 && nx >= -8 && nx <= 8);
            if (isfirst && inr) {
                int idx = atomicAdd(&sfast, 1);   // pack live entries first
                g_dfast[idx] = -ny * TSTRIDE - nx;
                g_wfast[idx] = (float)cnt * scale;
            }
            if (isfirst && !inr) {
                int idx = atomicAdd(&srare, 1);
                g_gsy[idx] = ny; g_gsx[idx] = nx;
                g_gw[idx] = (float)cnt * scale;
            }
        }
        __syncthreads();
        if (t == 0) {
            g_ng = srare;
            g_nf = sfast;
            g_C = ((float)Kk - red[0] / (float)(Pp * Pp)) / (float)(Kk - 1);
        }
        __syncthreads();
    }

    // ---- phase 1: horizontal sliding sum, 16 outputs/thread ----
    // task = (row r 0..142, seg 0..3 of 16 cols); 572 tasks, 512 threads.
    for (int tt = t; tt < 143 * 4; tt += 512) {
        int r   = tt >> 2;
        int seg = tt & 3;
        int arow = i0 - 15 + r;
        int jb = j0 + seg * 16;     // first of 16 output cols
        float o[16];
        if (arow < 0) {
            #pragma unroll
            for (int c = 0; c < 16; c++) o[c] = 0.f;
        } else {
            const float* row = img + (size_t)arow * Wd;
            float v[32];  // img cols jb-16 .. jb+15
            if (jb >= 16) {
                const float4* p = (const float4*)(row + jb - 16);
                #pragma unroll
                for (int q = 0; q < 8; q++) {
                    float4 f = __ldg(p + q);
                    v[4 * q + 0] = f.x; v[4 * q + 1] = f.y;
                    v[4 * q + 2] = f.z; v[4 * q + 3] = f.w;
                }
            } else {
                #pragma unroll
                for (int x = 0; x < 32; x++) {
                    int c = jb - 16 + x;
                    v[x] = (c >= 0) ? __ldg(row + c) : 0.f;
                }
            }
            float s = 0.f;
            #pragma unroll
            for (int x = 1; x <= 15; x++) s += v[x];
            o[0] = s;
            #pragma unroll
            for (int c = 1; c < 16; c++) { s += v[15 + c] - v[c]; o[c] = s; }
        }
        float* dst = rs + r * 65 + seg * 16;
        #pragma unroll
        for (int c = 0; c < 16; c++) dst[c] = o[c];
    }
    __syncthreads();

    // ---- phase 2: vertical sliding sum -> win (16-row chains, 512 thr) ----
    int col = t & 63;
    int R0  = (t >> 6) * 16;   // 0..112
    const float* cp = rs + col;
    float s = 0.f;
    #pragma unroll
    for (int r = 0; r < 15; r++) s += cp[(R0 + r) * 65];
    float* outp = g_win + (size_t)(i0 + R0) * Wd + j0 + col;
    #pragma unroll
    for (int rr = 0; rr < 16; rr++) {
        outp[(size_t)rr * Wd] = s;
        if (rr < 15)
            s += cp[(R0 + rr + 15) * 65] - cp[(R0 + rr) * 65];
    }
}

// ---------------------------------------------------------------------------
// Kernel 2: out[i,j] = C + sum_m w'_m * win[(i-sy)&M][(j-sx)&M]
// 32x128 tile/block, 512 threads (__launch_bounds__(512,4): same 2048
// threads/SM and regs=32 as the R8-proven shape, but halo staging
// redundancy drops 2.25x -> 1.69x and barrier count halves).
// 48x144 halo in SMEM (27.6KB). nf-variant fully-unrolled fast loop.
// grid = (16, 64); thread = 1 col x 8 rows (4 row-groups).
// ---------------------------------------------------------------------------
#define GATHER_LOOP(NM)                                        \
    _Pragma("unroll")                                          \
    for (int m = 0; m < (NM); m++) {                           \
        float w = sw[m];                                       \
        const float* p = base + sd[m];                         \
        _Pragma("unroll")                                      \
        for (int rr = 0; rr < 8; rr++)                         \
            acc[rr] += w * p[rr * TSTRIDE];                    \
    }

__global__ void __launch_bounds__(512, 4) k_gather(float* __restrict__ out) {
    __shared__ float tile[48 * TSTRIDE];
    __shared__ int   sd[Kk];
    __shared__ float sw[Kk];
    __shared__ int   sng, snf;
    __shared__ float sC;

    int t = threadIdx.x;
    int j0 = blockIdx.x * 128;
    int i0 = blockIdx.y * 32;

    if (t < Kk) { sd[t] = g_dfast[t]; sw[t] = g_wfast[t]; }
    if (t == 0) { sng = g_ng; snf = g_nf; sC = g_C; }

    // stage 48 x 144 halo via float4 (j0-8 ≡ 0 mod 4; wrap never splits)
    for (int idx = t; idx < 48 * 36; idx += 512) {
        int u  = idx / 36;
        int vq = idx - u * 36;
        int gr = (i0 - 8 + u) & MASKM;
        int gc = (j0 - 8 + 4 * vq) & MASKM;
        float4 f = __ldg((const float4*)(g_win + (size_t)gr * Wd + gc));
        *(float4*)&tile[u * TSTRIDE + 4 * vq] = f;
    }
    __syncthreads();

    int tx = t & 127;
    int R0 = (t >> 7) * 8;   // 0, 8, 16, 24
    const float* base = tile + (R0 + 8) * TSTRIDE + tx + 8;

    float acc[8];
    #pragma unroll
    for (int rr = 0; rr < 8; rr++) acc[rr] = 0.f;

    int nf = snf;
    if (nf <= 8)       { GATHER_LOOP(8)  }
    else if (nf <= 10) { GATHER_LOOP(10) }
    else if (nf <= 12) { GATHER_LOOP(12) }
    else if (nf <= 14) { GATHER_LOOP(14) }
    else               { GATHER_LOOP(16) }

    int ng = sng;
    if (ng > 0) {  // uniform, essentially never taken
        for (int m = 0; m < ng; m++) {
            int sy = g_gsy[m], sx = g_gsx[m];
            float w = g_gw[m];
            int gc = (j0 + tx - sx) & MASKM;
            #pragma unroll 1
            for (int rr = 0; rr < 8; rr++) {
                int gr = (i0 + R0 + rr - sy) & MASKM;
                acc[rr] += w * __ldg(g_win + (size_t)gr * Wd + gc);
            }
        }
    }

    float c = sC;
    float* op = out + (size_t)(i0 + R0) * Wd + j0 + tx;
    #pragma unroll
    for (int rr = 0; rr < 8; rr++)
        op[(size_t)rr * Wd] = c + acc[rr];
}

// ---------------------------------------------------------------------------
extern "C" void kernel_launch(void* const* d_in, const int* in_sizes, int n_in,
                              void* d_out, int out_size) {
    const float* x        = (const float*)d_in[0];  // (1,1,2048,2048)
    const float* patterns = (const float*)d_in[1];  // (16,15,15)
    const float* vectors  = (const float*)d_in[2];  // (16,2)
    float* out = (float*)d_out;                     // (2048,2048)

    k_box<<<dim3(32, 16), 512>>>(x, patterns, vectors);
    k_gather<<<dim3(16, 64), 512>>>(out);
}